// round 7
// baseline (speedup 1.0000x reference)
#include <cuda_runtime.h>
#include <cstdint>

// Dims: Nt=64, Nr=64, Mt=32, Mr=32, G^2=4096, num_sc=32, B=64, R=8, N_r_RF=4
#define G2 4096
typedef unsigned long long u64;

// ---- device globals (no allocation allowed) ----
// Dual-form tables (scaled 1/8):
//   g_W4[d*32+m] = (w.x, w.x, w.y, -w.y)   conj form:  acc += wxx*k + wyn*swap(k)
//   g_F4[c*32+a] = (f.x, f.x, -f.y, f.y)   mul  form
__device__ float4 g_W4[2048];
__device__ float4 g_F4[2048];
__device__ float2 g_S [(size_t)2048 * 4096];        // S[c*32+bp][g], 64 MB
__device__ float2 g_G1[(size_t)2048 * 2048];        // G1[b*32+m][c*32+s], 32 MB

// ---- f32x2 packed helpers ----
__device__ __forceinline__ u64 ffma2(u64 a, u64 b, u64 c) {
    u64 d; asm("fma.rn.f32x2 %0,%1,%2,%3;" : "=l"(d) : "l"(a), "l"(b), "l"(c)); return d;
}
__device__ __forceinline__ u64 fadd2(u64 a, u64 b) {
    u64 d; asm("add.rn.f32x2 %0,%1,%2;" : "=l"(d) : "l"(a), "l"(b)); return d;
}
__device__ __forceinline__ u64 swap2(u64 v) {
    uint2 t; asm("mov.b64 {%0,%1},%2;" : "=r"(t.x), "=r"(t.y) : "l"(v));
    u64 r;  asm("mov.b64 %0,{%1,%2};" : "=l"(r) : "r"(t.y), "r"(t.x));
    return r;
}
__device__ __forceinline__ uint32_t saddr(const void* p) {
    return (uint32_t)__cvta_generic_to_shared(p);
}
__device__ __forceinline__ void lds_v2(u64& a, u64& b, uint32_t addr) {
    asm volatile("ld.shared.v2.b64 {%0,%1},[%2];" : "=l"(a), "=l"(b) : "r"(addr));
}
__device__ __forceinline__ void ldg_v2(u64& a, u64& b, const void* p) {
    asm("ld.global.nc.v2.b64 {%0,%1},[%2];" : "=l"(a), "=l"(b) : "l"(p));
}
__device__ __forceinline__ void ldg_v2_c(u64& a, u64& b, const void* p) {
    asm volatile("ld.global.v2.b64 {%0,%1},[%2];" : "=l"(a), "=l"(b) : "l"(p));
}
__device__ __forceinline__ void stg_v2(void* p, u64 a, u64 b) {
    asm volatile("st.global.v2.b64 [%0],{%1,%2};" :: "l"(p), "l"(a), "l"(b));
}
__device__ __forceinline__ void ldg4(u64* k, const float2* p) {
    ldg_v2(k[0], k[1], p);
    ldg_v2(k[2], k[3], p + 2);
}

// ---- setup ----
__global__ void setup_kernel(const float* __restrict__ kW, const float* __restrict__ kF) {
    int i = blockIdx.x * blockDim.x + threadIdx.x;
    if (i < 2048) {
        float s, c;
        sincosf(kW[i], &s, &c);
        c *= 0.125f; s *= 0.125f;
        g_W4[i] = make_float4(c, c, s, -s);     // conj form
        sincosf(kF[i], &s, &c);
        c *= 0.125f; s *= 0.125f;
        g_F4[i] = make_float4(c, c, -s, s);     // mul form
    }
}

// =====================================================================
// Core: thread tile = 16 rows x 2 cols, reduce over 64.
// Per step: 16 LDS.v2 (broadcast, 16 wf) + 1 LDG.v2 (4 wf) + 2 swaps
//           + 64 FFMA2.  accs = 32 u64 = 64 regs. Depth-2 prefetch.
// WADDR includes the row-group offset; row i at +i*16, step dd at +dd*512.
// =====================================================================
#define CORE16x2(PTR, STRIDE, WADDR)                                         \
    u64 acc[16][2];                                                          \
    _Pragma("unroll")                                                        \
    for (int i = 0; i < 16; ++i) { acc[i][0] = 0ull; acc[i][1] = 0ull; }     \
    u64 ka0, ka1, kb0, kb1;                                                  \
    ldg_v2(ka0, ka1, PTR);                                                   \
    ldg_v2(kb0, kb1, (PTR) + (STRIDE));                                      \
    _Pragma("unroll 8")                                                      \
    for (int dd = 0; dd < 64; ++dd) {                                        \
        u64 kn0 = 0ull, kn1 = 0ull;                                          \
        if (dd + 2 < 64) ldg_v2(kn0, kn1, (PTR) + (size_t)(dd + 2) * (STRIDE)); \
        const u64 ks0 = swap2(ka0), ks1 = swap2(ka1);                        \
        _Pragma("unroll")                                                    \
        for (int i = 0; i < 16; ++i) {                                       \
            u64 wxx, wyn;                                                    \
            lds_v2(wxx, wyn, (WADDR) + (uint32_t)dd * 512 + i * 16);         \
            acc[i][0] = ffma2(wyn, ks0, ffma2(wxx, ka0, acc[i][0]));         \
            acc[i][1] = ffma2(wyn, ks1, ffma2(wxx, ka1, acc[i][1]));         \
        }                                                                    \
        ka0 = kb0; ka1 = kb1; kb0 = kn0; kb1 = kn1;                          \
    }

#define LOAD_TABLE(DST, SRC)                                                 \
    _Pragma("unroll")                                                        \
    for (int i = 0; i < 8; ++i) DST[threadIdx.x + 256 * i] = SRC[threadIdx.x + 256 * i]; \
    __syncthreads();

// =====================================================================
// sA: S[c*32+bp][g] = sum_d conj(W[d,bp]) * K[c*64+d][g]
// grid 1024 = (c=64, gt=16); 256 thr; gp = t&127 (256 g/block), bg = t>>7
// (2 groups x 16 bp). Tile 16bp x 2g.
// =====================================================================
__global__ void __launch_bounds__(256, 3) sA_kernel(const float2* __restrict__ K) {
    __shared__ float4 Wt[2048];
    LOAD_TABLE(Wt, g_W4)

    const int t = threadIdx.x;
    const int c = blockIdx.x >> 4, gt = blockIdx.x & 15;
    const int gp = t & 127, bg = t >> 7;
    const int g = gt * 256 + gp * 2;

    const float2* Kp = K + (size_t)(c * 64) * G2 + g;
    const uint32_t waddr = saddr(Wt) + (uint32_t)bg * 256;

    CORE16x2(Kp, G2, waddr)

#pragma unroll
    for (int i = 0; i < 16; ++i) {
        float2* Sp = g_S + (size_t)(c * 32 + bg * 16 + i) * G2 + g;
        stg_v2(Sp, acc[i][0], acc[i][1]);
    }
}

// =====================================================================
// phiB: Phi[(a*32+bp)][g] = sum_c F[c,a] * S[c*32+bp][g]
// grid 512 = (bp=32, gt=16); tile 16a x 2g.
// =====================================================================
__global__ void __launch_bounds__(256, 3) phiB_kernel(float2* __restrict__ Phi) {
    __shared__ float4 Ft[2048];
    LOAD_TABLE(Ft, g_F4)

    const int t = threadIdx.x;
    const int bp = blockIdx.x >> 4, gt = blockIdx.x & 15;
    const int gp = t & 127, ag = t >> 7;
    const int g = gt * 256 + gp * 2;

    const float2* Sp = g_S + (size_t)bp * G2 + g;          // + c*32*G2
    const uint32_t faddr = saddr(Ft) + (uint32_t)ag * 256;

    CORE16x2(Sp, (size_t)32 * G2, faddr)

#pragma unroll
    for (int i = 0; i < 16; ++i) {
        float2* Pp = Phi + (size_t)((ag * 16 + i) * 32 + bp) * G2 + g;
        stg_v2(Pp, acc[i][0], acc[i][1]);
    }
}

// =====================================================================
// y1: G1[b*32+m][cs] = sum_d conj(W[d,m]) * H[b][d][cs]
// grid 512 = (b=64, cst=8); tile 16m x 2cs (cs-tile 256).
// =====================================================================
__global__ void __launch_bounds__(256, 3) y1_kernel(const float2* __restrict__ H) {
    __shared__ float4 Wt[2048];
    LOAD_TABLE(Wt, g_W4)

    const int t = threadIdx.x;
    const int b = blockIdx.x >> 3, cst = blockIdx.x & 7;
    const int csp = t & 127, mg = t >> 7;
    const int cs = cst * 256 + csp * 2;

    const float2* Hp = H + (size_t)b * 131072 + cs;        // + d*2048
    const uint32_t waddr = saddr(Wt) + (uint32_t)mg * 256;

    CORE16x2(Hp, 2048, waddr)

#pragma unroll
    for (int i = 0; i < 16; ++i) {
        float2* Gp = g_G1 + (size_t)(b * 32 + mg * 16 + i) * 2048 + cs;
        stg_v2(Gp, acc[i][0], acc[i][1]);
    }
}

// =====================================================================
// y2s: Y[b][(a*32+m)][s] = sum_c F[c,a] * G1[b*32+m][c*32+s]
// grid 256: 8 (b,m) per block; per (b,m) 32 thr = 16 s-pairs x 2 a-groups;
// tile 16a x 2s.
// =====================================================================
__global__ void __launch_bounds__(256, 3) y2s_kernel(float2* __restrict__ Y) {
    __shared__ float4 Ft[2048];
    LOAD_TABLE(Ft, g_F4)

    const int t = threadIdx.x;
    const int bm = blockIdx.x * 8 + (t >> 5);
    const int b = bm >> 5, m = bm & 31;
    const int sub = t & 31;
    const int sp = sub & 15, ag = sub >> 4;
    const int s = sp * 2;

    const float2* Gp = g_G1 + (size_t)bm * 2048 + s;       // + c*32
    const uint32_t faddr = saddr(Ft) + (uint32_t)ag * 256;

    CORE16x2(Gp, 32, faddr)

#pragma unroll
    for (int i = 0; i < 16; ++i) {
        float2* yp = Y + (size_t)(b * 1024 + (ag * 16 + i) * 32 + m) * 32 + s;
        stg_v2(yp, acc[i][0], acc[i][1]);
    }
}

// =====================================================================
// y2n: Y[b][a*32 + r*4 + j][s] += sum_n conj(W[n, r*4+j]) * noise[b,r,n,x]
// x = a*32+s; grid 512 = (b,r); thread owns x-quad (x0 = t*4) and 4 j.
// Pure 256 MB DRAM stream + RMW tail. Runs after y2s.
// =====================================================================
__global__ void __launch_bounds__(256) y2n_kernel(const float2* __restrict__ noise,
                                                  float2* __restrict__ Y) {
    __shared__ float4 Wn[256];   // [n*4+j] = (x,x,y,-y)
    const int t = threadIdx.x;
    const int b = blockIdx.x >> 3, r = blockIdx.x & 7;
    Wn[t] = g_W4[(t >> 2) * 32 + r * 4 + (t & 3)];
    __syncthreads();

    const int x0 = t * 4;
    const uint32_t wn = saddr(Wn);
    const float2* np = noise + (size_t)(b * 8 + r) * 65536 + x0;

    u64 acc[4][4];
#pragma unroll
    for (int j = 0; j < 4; ++j)
#pragma unroll
        for (int q = 0; q < 4; ++q) acc[j][q] = 0ull;

#pragma unroll 4
    for (int n = 0; n < 64; ++n) {
        u64 v[4];
        ldg4(v, np + (size_t)n * 1024);
        const u64 w0 = swap2(v[0]), w1 = swap2(v[1]), w2 = swap2(v[2]), w3 = swap2(v[3]);
#pragma unroll
        for (int j = 0; j < 4; ++j) {
            u64 wxx, wyn;
            lds_v2(wxx, wyn, wn + (uint32_t)((n * 4 + j) << 4));
            acc[j][0] = ffma2(wyn, w0, ffma2(wxx, v[0], acc[j][0]));
            acc[j][1] = ffma2(wyn, w1, ffma2(wxx, v[1], acc[j][1]));
            acc[j][2] = ffma2(wyn, w2, ffma2(wxx, v[2], acc[j][2]));
            acc[j][3] = ffma2(wyn, w3, ffma2(wxx, v[3], acc[j][3]));
        }
    }

    const int a = x0 >> 5, s = x0 & 31;
#pragma unroll
    for (int j = 0; j < 4; ++j) {
        float2* yp = Y + (size_t)(b * 1024 + a * 32 + r * 4 + j) * 32 + s;
        u64 y0, y1, y2, y3;
        ldg_v2_c(y0, y1, yp);
        ldg_v2_c(y2, y3, yp + 2);
        stg_v2(yp,     fadd2(y0, acc[j][0]), fadd2(y1, acc[j][1]));
        stg_v2(yp + 2, fadd2(y2, acc[j][2]), fadd2(y3, acc[j][3]));
    }
}

extern "C" void kernel_launch(void* const* d_in, const int* in_sizes, int n_in,
                              void* d_out, int out_size) {
    const float2* H     = (const float2*)d_in[0];  // (64,64,64,32,2) f32
    const float2* noise = (const float2*)d_in[1];  // (64,8,64,1024,2) f32
    const float*  kW    = (const float*)d_in[2];   // (64,32)
    const float*  kF    = (const float*)d_in[3];   // (64,32)
    const float2* K     = (const float2*)d_in[4];  // (4096,4096,2)

    float2* Phi = (float2*)d_out;                   // 1024*4096 complex
    float2* Y   = Phi + (size_t)1024 * 4096;        // 64*1024*32 complex

    setup_kernel<<<8, 256>>>(kW, kF);
    sA_kernel  <<<1024, 256>>>(K);
    y1_kernel  <<<512, 256>>>(H);
    phiB_kernel<<<512, 256>>>(Phi);
    y2s_kernel <<<256, 256>>>(Y);
    y2n_kernel <<<512, 256>>>(noise, Y);
}

// round 8
// speedup vs baseline: 1.0676x; 1.0676x over previous
#include <cuda_runtime.h>
#include <cstdint>

// Dims: Nt=64, Nr=64, Mt=32, Mr=32, G^2=4096, num_sc=32, B=64, R=8, N_r_RF=4
#define G2 4096
typedef unsigned long long u64;

// ---- device globals (no allocation allowed) ----
// Dual-form tables (scaled 1/8), entry = float4:
//   W: (w.x, w.x, w.y, -w.y)   conj form:  acc += wxx*k + wyn*swap(k)
//   F: (f.x, f.x, -f.y, f.y)   mul  form
__device__ float4 g_W4[2048];
__device__ float4 g_F4[2048];
__device__ float2 g_S [(size_t)2048 * 4096];        // S[c*32+bp][g], 64 MB
__device__ float2 g_G1[(size_t)2048 * 2048];        // G1[b*32+m][c*32+s], 32 MB

// Constant-space copies (read via warp-uniform indices -> LDCU, uniform pipe)
__constant__ double2 c_W4[2048];    // .x bits = (x,x), .y bits = (y,-y)
__constant__ double2 c_F4[2048];

// ---- f32x2 packed helpers ----
__device__ __forceinline__ u64 ffma2(u64 a, u64 b, u64 c) {
    u64 d; asm("fma.rn.f32x2 %0,%1,%2,%3;" : "=l"(d) : "l"(a), "l"(b), "l"(c)); return d;
}
__device__ __forceinline__ u64 fadd2(u64 a, u64 b) {
    u64 d; asm("add.rn.f32x2 %0,%1,%2;" : "=l"(d) : "l"(a), "l"(b)); return d;
}
__device__ __forceinline__ u64 swap2(u64 v) {
    uint2 t; asm("mov.b64 {%0,%1},%2;" : "=r"(t.x), "=r"(t.y) : "l"(v));
    u64 r;  asm("mov.b64 %0,{%1,%2};" : "=l"(r) : "r"(t.y), "r"(t.x));
    return r;
}
__device__ __forceinline__ uint32_t saddr(const void* p) {
    return (uint32_t)__cvta_generic_to_shared(p);
}
__device__ __forceinline__ void lds_v2(u64& a, u64& b, uint32_t addr) {
    asm volatile("ld.shared.v2.b64 {%0,%1},[%2];" : "=l"(a), "=l"(b) : "r"(addr));
}
__device__ __forceinline__ void ldg_v2(u64& a, u64& b, const void* p) {
    asm("ld.global.nc.v2.b64 {%0,%1},[%2];" : "=l"(a), "=l"(b) : "l"(p));
}
__device__ __forceinline__ void ldg_v2_c(u64& a, u64& b, const void* p) {
    asm volatile("ld.global.v2.b64 {%0,%1},[%2];" : "=l"(a), "=l"(b) : "l"(p));
}
__device__ __forceinline__ void stg_v2(void* p, u64 a, u64 b) {
    asm volatile("st.global.v2.b64 [%0],{%1,%2};" :: "l"(p), "l"(a), "l"(b));
}
__device__ __forceinline__ void ldg4(u64* k, const float2* p) {
    ldg_v2(k[0], k[1], p);
    ldg_v2(k[2], k[3], p + 2);
}

// ---- setup ----
__global__ void setup_kernel(const float* __restrict__ kW, const float* __restrict__ kF) {
    int i = blockIdx.x * blockDim.x + threadIdx.x;
    if (i < 2048) {
        float s, c;
        sincosf(kW[i], &s, &c);
        c *= 0.125f; s *= 0.125f;
        g_W4[i] = make_float4(c, c, s, -s);     // conj form
        sincosf(kF[i], &s, &c);
        c *= 0.125f; s *= 0.125f;
        g_F4[i] = make_float4(c, c, -s, s);     // mul form
    }
}

// =====================================================================
// Core: thread tile = 8 rows x 2 cols, reduce over 64, R4-proven config,
// but coefficients from __constant__ with warp-uniform index (LDCU path):
// per dd: 8 LDCU.128 (uniform pipe) + 1 LDG.v2 + 2 swaps + 32 FFMA2.
// RBASE is warp-uniform (derived from t>>6); dd is loop-uniform.
// =====================================================================
#define CORE8x2C(PTR, STRIDE, TAB, RBASE)                                    \
    u64 acc0[8], acc1[8];                                                    \
    _Pragma("unroll")                                                        \
    for (int i = 0; i < 8; ++i) { acc0[i] = 0ull; acc1[i] = 0ull; }          \
    u64 ka0, ka1, kb0, kb1;                                                  \
    ldg_v2(ka0, ka1, PTR);                                                   \
    ldg_v2(kb0, kb1, (PTR) + (STRIDE));                                      \
    _Pragma("unroll 2")                                                      \
    for (int dd = 0; dd < 64; ++dd) {                                        \
        u64 kn0 = 0ull, kn1 = 0ull;                                          \
        if (dd + 2 < 64) ldg_v2(kn0, kn1, (PTR) + (size_t)(dd + 2) * (STRIDE)); \
        const u64 ks0 = swap2(ka0), ks1 = swap2(ka1);                        \
        _Pragma("unroll")                                                    \
        for (int i = 0; i < 8; ++i) {                                        \
            const double2 w = (TAB)[(RBASE) + dd * 32 + i];                  \
            const u64 wxx = __double_as_longlong(w.x);                       \
            const u64 wyn = __double_as_longlong(w.y);                       \
            acc0[i] = ffma2(wyn, ks0, ffma2(wxx, ka0, acc0[i]));             \
            acc1[i] = ffma2(wyn, ks1, ffma2(wxx, ka1, acc1[i]));             \
        }                                                                    \
        ka0 = kb0; ka1 = kb1; kb0 = kn0; kb1 = kn1;                          \
    }

// =====================================================================
// K1 (conj-W), grid 3072:
//  blocks [0,2048):  sA:  S[c*32+bp][g]  = sum_d conj(W[d,bp]) * K[c*64+d][g]
//                    blk = (c=64, gt=32); tile 8bp x 2g; 128 g/block.
//  blocks [2048,3072): y1: G1[b*32+m][cs] = sum_d conj(W[d,m]) * H[b][d][cs]
//                    blk' = (b=64, cst=16); tile 8m x 2cs; 128 cs/block.
// =====================================================================
__global__ void __launch_bounds__(256) k1_kernel(const float2* __restrict__ K,
                                                 const float2* __restrict__ H) {
    const int t = threadIdx.x;
    const int grp = t >> 6;            // warp-uniform row group (0..3)
    const int col = t & 63;
    const int rbase = grp * 8;

    if (blockIdx.x < 2048) {
        const int c = blockIdx.x >> 5, gt = blockIdx.x & 31;
        const int g = gt * 128 + col * 2;
        const float2* Kp = K + (size_t)(c * 64) * G2 + g;

        CORE8x2C(Kp, G2, c_W4, rbase)

#pragma unroll
        for (int i = 0; i < 8; ++i) {
            float2* Sp = g_S + (size_t)(c * 32 + rbase + i) * G2 + g;
            stg_v2(Sp, acc0[i], acc1[i]);
        }
    } else {
        const int blk = blockIdx.x - 2048;
        const int b = blk >> 4, cst = blk & 15;
        const int cs = cst * 128 + col * 2;
        const float2* Hp = H + (size_t)b * 131072 + cs;    // + d*2048

        CORE8x2C(Hp, 2048, c_W4, rbase)

#pragma unroll
        for (int i = 0; i < 8; ++i) {
            float2* Gp = g_G1 + (size_t)(b * 32 + rbase + i) * 2048 + cs;
            stg_v2(Gp, acc0[i], acc1[i]);
        }
    }
}

// =====================================================================
// K2 (mul-F), grid 1536:
//  blocks [0,1024):  phiB: Phi[(a*32+bp)][g] = sum_c F[c,a] * S[c*32+bp][g]
//                    blk = (bp=32, gt=32); tile 8a x 2g (constant table).
//  blocks [1024,1536): y2s: Y[b][(a*32+m)][s] = sum_c F[c,a]*G1[b*32+m][c*32+s]
//                    4 (b,m) per block; shared table (index not warp-uniform).
// =====================================================================
__global__ void __launch_bounds__(256) k2_kernel(float2* __restrict__ Phi,
                                                 float2* __restrict__ Y) {
    __shared__ float4 Ft[2048];
    const int t = threadIdx.x;

    if (blockIdx.x < 1024) {
        const int grp = t >> 6;        // warp-uniform
        const int col = t & 63;
        const int rbase = grp * 8;
        const int bp = blockIdx.x >> 5, gt = blockIdx.x & 31;
        const int g = gt * 128 + col * 2;
        const float2* Sp = g_S + (size_t)bp * G2 + g;      // + c*32*G2

        CORE8x2C(Sp, (size_t)32 * G2, c_F4, rbase)

#pragma unroll
        for (int i = 0; i < 8; ++i) {
            float2* Pp = Phi + (size_t)((rbase + i) * 32 + bp) * G2 + g;
            stg_v2(Pp, acc0[i], acc1[i]);
        }
    } else {
#pragma unroll
        for (int i = 0; i < 8; ++i) Ft[t + 256 * i] = g_F4[t + 256 * i];
        __syncthreads();

        const int bm = (blockIdx.x - 1024) * 4 + (t >> 6);
        const int b = bm >> 5, m = bm & 31;
        const int sp = t & 15, ag = (t >> 4) & 3;
        const int s = sp * 2;

        const float2* Gp = g_G1 + (size_t)bm * 2048 + s;   // + c*32
        const uint32_t faddr = saddr(Ft) + (uint32_t)(ag * 8) * 16;

        u64 acc0[8], acc1[8];
#pragma unroll
        for (int i = 0; i < 8; ++i) { acc0[i] = 0ull; acc1[i] = 0ull; }
        u64 ka0, ka1, kb0, kb1;
        ldg_v2(ka0, ka1, Gp);
        ldg_v2(kb0, kb1, Gp + 32);

#pragma unroll 2
        for (int c = 0; c < 64; ++c) {
            u64 kn0 = 0ull, kn1 = 0ull;
            if (c + 2 < 64) ldg_v2(kn0, kn1, Gp + (size_t)(c + 2) * 32);
            const u64 ks0 = swap2(ka0), ks1 = swap2(ka1);
#pragma unroll
            for (int i = 0; i < 8; ++i) {
                u64 fxx, fyn;
                lds_v2(fxx, fyn, faddr + (uint32_t)c * 512 + i * 16);
                acc0[i] = ffma2(fyn, ks0, ffma2(fxx, ka0, acc0[i]));
                acc1[i] = ffma2(fyn, ks1, ffma2(fxx, ka1, acc1[i]));
            }
            ka0 = kb0; ka1 = kb1; kb0 = kn0; kb1 = kn1;
        }

#pragma unroll
        for (int i = 0; i < 8; ++i) {
            float2* yp = Y + (size_t)(b * 1024 + (ag * 8 + i) * 32 + m) * 32 + s;
            stg_v2(yp, acc0[i], acc1[i]);
        }
    }
}

// =====================================================================
// y2n: Y[b][a*32 + r*4 + j][s] += sum_n conj(W[n, r*4+j]) * noise[b,r,n,x]
// x = a*32+s; grid 512 = (b,r); thread owns x-quad (x0 = t*4) and 4 j.
// Pure 256 MB DRAM stream + RMW tail. Runs after K2.
// =====================================================================
__global__ void __launch_bounds__(256) y2n_kernel(const float2* __restrict__ noise,
                                                  float2* __restrict__ Y) {
    __shared__ float4 Wn[256];   // [n*4+j] = (x,x,y,-y)
    const int t = threadIdx.x;
    const int b = blockIdx.x >> 3, r = blockIdx.x & 7;
    Wn[t] = g_W4[(t >> 2) * 32 + r * 4 + (t & 3)];
    __syncthreads();

    const int x0 = t * 4;
    const uint32_t wn = saddr(Wn);
    const float2* np = noise + (size_t)(b * 8 + r) * 65536 + x0;

    u64 acc[4][4];
#pragma unroll
    for (int j = 0; j < 4; ++j)
#pragma unroll
        for (int q = 0; q < 4; ++q) acc[j][q] = 0ull;

#pragma unroll 4
    for (int n = 0; n < 64; ++n) {
        u64 v[4];
        ldg4(v, np + (size_t)n * 1024);
        const u64 w0 = swap2(v[0]), w1 = swap2(v[1]), w2 = swap2(v[2]), w3 = swap2(v[3]);
#pragma unroll
        for (int j = 0; j < 4; ++j) {
            u64 wxx, wyn;
            lds_v2(wxx, wyn, wn + (uint32_t)((n * 4 + j) << 4));
            acc[j][0] = ffma2(wyn, w0, ffma2(wxx, v[0], acc[j][0]));
            acc[j][1] = ffma2(wyn, w1, ffma2(wxx, v[1], acc[j][1]));
            acc[j][2] = ffma2(wyn, w2, ffma2(wxx, v[2], acc[j][2]));
            acc[j][3] = ffma2(wyn, w3, ffma2(wxx, v[3], acc[j][3]));
        }
    }

    const int a = x0 >> 5, s = x0 & 31;
#pragma unroll
    for (int j = 0; j < 4; ++j) {
        float2* yp = Y + (size_t)(b * 1024 + a * 32 + r * 4 + j) * 32 + s;
        u64 y0, y1, y2, y3;
        ldg_v2_c(y0, y1, yp);
        ldg_v2_c(y2, y3, yp + 2);
        stg_v2(yp,     fadd2(y0, acc[j][0]), fadd2(y1, acc[j][1]));
        stg_v2(yp + 2, fadd2(y2, acc[j][2]), fadd2(y3, acc[j][3]));
    }
}

extern "C" void kernel_launch(void* const* d_in, const int* in_sizes, int n_in,
                              void* d_out, int out_size) {
    const float2* H     = (const float2*)d_in[0];  // (64,64,64,32,2) f32
    const float2* noise = (const float2*)d_in[1];  // (64,8,64,1024,2) f32
    const float*  kW    = (const float*)d_in[2];   // (64,32)
    const float*  kF    = (const float*)d_in[3];   // (64,32)
    const float2* K     = (const float2*)d_in[4];  // (4096,4096,2)

    float2* Phi = (float2*)d_out;                   // 1024*4096 complex
    float2* Y   = Phi + (size_t)1024 * 4096;        // 64*1024*32 complex

    void* pW = nullptr; void* pF = nullptr;
    cudaGetSymbolAddress(&pW, g_W4);
    cudaGetSymbolAddress(&pF, g_F4);

    setup_kernel<<<8, 256>>>(kW, kF);
    cudaMemcpyToSymbolAsync(c_W4, pW, 2048 * sizeof(double2), 0,
                            cudaMemcpyDeviceToDevice, 0);
    cudaMemcpyToSymbolAsync(c_F4, pF, 2048 * sizeof(double2), 0,
                            cudaMemcpyDeviceToDevice, 0);
    k1_kernel <<<3072, 256>>>(K, H);
    k2_kernel <<<1536, 256>>>(Phi, Y);
    y2n_kernel<<<512, 256>>>(noise, Y);
}

// round 9
// speedup vs baseline: 1.4844x; 1.3904x over previous
#include <cuda_runtime.h>
#include <cstdint>

// Dims: Nt=64, Nr=64, Mt=32, Mr=32, G^2=4096, num_sc=32, B=64, R=8, N_r_RF=4
#define G2 4096
typedef unsigned long long u64;

// ---- device globals (no allocation allowed) ----
// Dual-form tables (scaled 1/8):
//   g_W4[d*32+m] = (w.x, w.x, w.y, -w.y)   conj form:  acc += wxx*k + wyn*swap(k)
//   g_F4[c*32+a] = (f.x, f.x, -f.y, f.y)   mul  form
__device__ float4 g_W4[2048];
__device__ float4 g_F4[2048];
__device__ float2 g_S [(size_t)2048 * 4096];        // S[c*32+bp][g], 64 MB
__device__ float2 g_G1[(size_t)2048 * 2048];        // G1[b*32+m][c*32+s], 32 MB

// ---- f32x2 packed helpers ----
__device__ __forceinline__ u64 ffma2(u64 a, u64 b, u64 c) {
    u64 d; asm("fma.rn.f32x2 %0,%1,%2,%3;" : "=l"(d) : "l"(a), "l"(b), "l"(c)); return d;
}
__device__ __forceinline__ u64 fadd2(u64 a, u64 b) {
    u64 d; asm("add.rn.f32x2 %0,%1,%2;" : "=l"(d) : "l"(a), "l"(b)); return d;
}
__device__ __forceinline__ u64 swap2(u64 v) {
    uint2 t; asm("mov.b64 {%0,%1},%2;" : "=r"(t.x), "=r"(t.y) : "l"(v));
    u64 r;  asm("mov.b64 %0,{%1,%2};" : "=l"(r) : "r"(t.y), "r"(t.x));
    return r;
}
__device__ __forceinline__ uint32_t saddr(const void* p) {
    return (uint32_t)__cvta_generic_to_shared(p);
}
__device__ __forceinline__ void lds_v2(u64& a, u64& b, uint32_t addr) {
    asm volatile("ld.shared.v2.b64 {%0,%1},[%2];" : "=l"(a), "=l"(b) : "r"(addr));
}
__device__ __forceinline__ void ldg_v2(u64& a, u64& b, const void* p) {
    asm("ld.global.nc.v2.b64 {%0,%1},[%2];" : "=l"(a), "=l"(b) : "l"(p));
}
__device__ __forceinline__ void ldg_v2_c(u64& a, u64& b, const void* p) {
    asm volatile("ld.global.v2.b64 {%0,%1},[%2];" : "=l"(a), "=l"(b) : "l"(p));
}
__device__ __forceinline__ void stg_v2(void* p, u64 a, u64 b) {
    asm volatile("st.global.v2.b64 [%0],{%1,%2};" :: "l"(p), "l"(a), "l"(b));
}
__device__ __forceinline__ void ldg4(u64* k, const float2* p) {
    ldg_v2(k[0], k[1], p);
    ldg_v2(k[2], k[3], p + 2);
}

// ---- setup ----
__global__ void setup_kernel(const float* __restrict__ kW, const float* __restrict__ kF) {
    int i = blockIdx.x * blockDim.x + threadIdx.x;
    if (i < 2048) {
        float s, c;
        sincosf(kW[i], &s, &c);
        c *= 0.125f; s *= 0.125f;
        g_W4[i] = make_float4(c, c, s, -s);     // conj form
        sincosf(kF[i], &s, &c);
        c *= 0.125f; s *= 0.125f;
        g_F4[i] = make_float4(c, c, -s, s);     // mul form
    }
}

// =====================================================================
// R4-proven core: thread tile = 8 rows x 2 cols, reduce over 64.
// Per dd: 8 LDS.v2(16B bcast) + 1 LDG.v2(16B) + 2 swaps + 32 FFMA2.
// TADDR: shared table base incl. row-group offset; row i at +i*16,
// step dd at +dd*512. Depth-2 prefetch, unroll 2.
// =====================================================================
#define CORE8x2(PTR, STRIDE, TADDR)                                          \
    u64 acc0[8], acc1[8];                                                    \
    _Pragma("unroll")                                                        \
    for (int i = 0; i < 8; ++i) { acc0[i] = 0ull; acc1[i] = 0ull; }          \
    u64 ka0, ka1, kb0, kb1;                                                  \
    ldg_v2(ka0, ka1, PTR);                                                   \
    ldg_v2(kb0, kb1, (PTR) + (STRIDE));                                      \
    _Pragma("unroll 2")                                                      \
    for (int dd = 0; dd < 64; ++dd) {                                        \
        u64 kn0 = 0ull, kn1 = 0ull;                                          \
        if (dd + 2 < 64) ldg_v2(kn0, kn1, (PTR) + (size_t)(dd + 2) * (STRIDE)); \
        const u64 ks0 = swap2(ka0), ks1 = swap2(ka1);                        \
        _Pragma("unroll")                                                    \
        for (int i = 0; i < 8; ++i) {                                        \
            u64 wxx, wyn;                                                    \
            lds_v2(wxx, wyn, (TADDR) + (uint32_t)dd * 512 + i * 16);         \
            acc0[i] = ffma2(wyn, ks0, ffma2(wxx, ka0, acc0[i]));             \
            acc1[i] = ffma2(wyn, ks1, ffma2(wxx, ka1, acc1[i]));             \
        }                                                                    \
        ka0 = kb0; ka1 = kb1; kb0 = kn0; kb1 = kn1;                          \
    }

#define LOAD_TABLE(DST, SRC)                                                 \
    _Pragma("unroll")                                                        \
    for (int i = 0; i < 8; ++i) DST[threadIdx.x + 256 * i] = SRC[threadIdx.x + 256 * i]; \
    __syncthreads();

// =====================================================================
// k1, grid 3584, striped: blockIdx%7==6 -> y2n (512 blocks, DRAM-bound),
// else other_id = blockIdx - blockIdx/7:
//   [0,2048):  sA:  S[c*32+bp][g] = sum_d conj(W[d,bp]) * K[c*64+d][g]
//   [2048,3072): y1: G1[b*32+m][cs] = sum_d conj(W[d,m]) * H[b][d][cs]
// y2n WRITES Y (init): Y[b][a*32+r*4+j][s] = sum_n conj(W[n,r4j])*noise
// =====================================================================
__global__ void __launch_bounds__(256) k1_kernel(const float2* __restrict__ K,
                                                 const float2* __restrict__ H,
                                                 const float2* __restrict__ noise,
                                                 float2* __restrict__ Y) {
    __shared__ float4 Tab[2048];
    const int t = threadIdx.x;
    const unsigned bid = blockIdx.x;

    if (bid % 7u == 6u) {
        // ---------------- y2n ----------------
        const int blk = bid / 7u;                 // 0..511
        const int b = blk >> 3, r = blk & 7;
        Tab[t] = g_W4[(t >> 2) * 32 + r * 4 + (t & 3)];   // Wn[n*4+j]
        __syncthreads();

        const int x0 = t * 4;
        const uint32_t wn = saddr(Tab);
        const float2* np = noise + (size_t)(b * 8 + r) * 65536 + x0;

        u64 acc[4][4];
#pragma unroll
        for (int j = 0; j < 4; ++j)
#pragma unroll
            for (int q = 0; q < 4; ++q) acc[j][q] = 0ull;

#pragma unroll 4
        for (int n = 0; n < 64; ++n) {
            u64 v[4];
            ldg4(v, np + (size_t)n * 1024);
            const u64 w0 = swap2(v[0]), w1 = swap2(v[1]),
                      w2 = swap2(v[2]), w3 = swap2(v[3]);
#pragma unroll
            for (int j = 0; j < 4; ++j) {
                u64 wxx, wyn;
                lds_v2(wxx, wyn, wn + (uint32_t)((n * 4 + j) << 4));
                acc[j][0] = ffma2(wyn, w0, ffma2(wxx, v[0], acc[j][0]));
                acc[j][1] = ffma2(wyn, w1, ffma2(wxx, v[1], acc[j][1]));
                acc[j][2] = ffma2(wyn, w2, ffma2(wxx, v[2], acc[j][2]));
                acc[j][3] = ffma2(wyn, w3, ffma2(wxx, v[3], acc[j][3]));
            }
        }

        const int a = x0 >> 5, s = x0 & 31;
#pragma unroll
        for (int j = 0; j < 4; ++j) {
            float2* yp = Y + (size_t)(b * 1024 + a * 32 + r * 4 + j) * 32 + s;
            stg_v2(yp,     acc[j][0], acc[j][1]);     // WRITE (init)
            stg_v2(yp + 2, acc[j][2], acc[j][3]);
        }
        return;
    }

    // non-y2n blocks: shared W table
    LOAD_TABLE(Tab, g_W4)
    const int oid = bid - bid / 7u;               // 0..3071
    const int gp = t & 63, rg = t >> 6;
    const uint32_t taddr = saddr(Tab) + (uint32_t)(rg * 8) * 16;

    if (oid < 2048) {
        // ---------------- sA ----------------
        const int c = oid >> 5, gt = oid & 31;
        const int g = gt * 128 + gp * 2;
        const float2* Kp = K + (size_t)(c * 64) * G2 + g;

        CORE8x2(Kp, G2, taddr)

#pragma unroll
        for (int i = 0; i < 8; ++i) {
            float2* Sp = g_S + (size_t)(c * 32 + rg * 8 + i) * G2 + g;
            stg_v2(Sp, acc0[i], acc1[i]);
        }
    } else {
        // ---------------- y1 ----------------
        const int blk = oid - 2048;
        const int b = blk >> 4, cst = blk & 15;
        const int cs = cst * 128 + gp * 2;
        const float2* Hp = H + (size_t)b * 131072 + cs;    // + d*2048

        CORE8x2(Hp, 2048, taddr)

#pragma unroll
        for (int i = 0; i < 8; ++i) {
            float2* Gp = g_G1 + (size_t)(b * 32 + rg * 8 + i) * 2048 + cs;
            stg_v2(Gp, acc0[i], acc1[i]);
        }
    }
}

// =====================================================================
// k2, grid 1536, striped: blockIdx%3==2 -> y2s (512 blocks, RMW),
// else phi_id = blockIdx - blockIdx/3 in [0,1024):
//   phiB: Phi[(a*32+bp)][g] = sum_c F[c,a] * S[c*32+bp][g]
//   y2s:  Y[b][(a*32+m)][s] += sum_c F[c,a] * G1[b*32+m][c*32+s]
// =====================================================================
__global__ void __launch_bounds__(256) k2_kernel(float2* __restrict__ Phi,
                                                 float2* __restrict__ Y) {
    __shared__ float4 Ft[2048];
    const int t = threadIdx.x;
    const unsigned bid = blockIdx.x;
    LOAD_TABLE(Ft, g_F4)

    if (bid % 3u == 2u) {
        // ---------------- y2s (RMW) ----------------
        const int blk = bid / 3u;                 // 0..511
        const int bm = blk * 4 + (t >> 6);
        const int b = bm >> 5, m = bm & 31;
        const int sp = t & 15, ag = (t >> 4) & 3;
        const int s = sp * 2;

        const float2* Gp = g_G1 + (size_t)bm * 2048 + s;   // + c*32
        const uint32_t faddr = saddr(Ft) + (uint32_t)(ag * 8) * 16;

        CORE8x2(Gp, 32, faddr)

#pragma unroll
        for (int i = 0; i < 8; ++i) {
            float2* yp = Y + (size_t)(b * 1024 + (ag * 8 + i) * 32 + m) * 32 + s;
            u64 y0, y1;
            ldg_v2_c(y0, y1, yp);
            stg_v2(yp, fadd2(y0, acc0[i]), fadd2(y1, acc1[i]));
        }
    } else {
        // ---------------- phiB ----------------
        const int pid = bid - bid / 3u;           // 0..1023
        const int gp = t & 63, ag = t >> 6;
        const int bp = pid >> 5, gt = pid & 31;
        const int g = gt * 128 + gp * 2;

        const float2* Sp = g_S + (size_t)bp * G2 + g;      // + c*32*G2
        const uint32_t faddr = saddr(Ft) + (uint32_t)(ag * 8) * 16;

        CORE8x2(Sp, (size_t)32 * G2, faddr)

#pragma unroll
        for (int i = 0; i < 8; ++i) {
            float2* Pp = Phi + (size_t)((ag * 8 + i) * 32 + bp) * G2 + g;
            stg_v2(Pp, acc0[i], acc1[i]);
        }
    }
}

extern "C" void kernel_launch(void* const* d_in, const int* in_sizes, int n_in,
                              void* d_out, int out_size) {
    const float2* H     = (const float2*)d_in[0];  // (64,64,64,32,2) f32
    const float2* noise = (const float2*)d_in[1];  // (64,8,64,1024,2) f32
    const float*  kW    = (const float*)d_in[2];   // (64,32)
    const float*  kF    = (const float*)d_in[3];   // (64,32)
    const float2* K     = (const float2*)d_in[4];  // (4096,4096,2)

    float2* Phi = (float2*)d_out;                   // 1024*4096 complex
    float2* Y   = Phi + (size_t)1024 * 4096;        // 64*1024*32 complex

    setup_kernel<<<8, 256>>>(kW, kF);
    k1_kernel<<<3584, 256>>>(K, H, noise, Y);
    k2_kernel<<<1536, 256>>>(Phi, Y);
}